// round 9
// baseline (speedup 1.0000x reference)
#include <cuda_runtime.h>
#include <cuda_bf16.h>
#include <math.h>
#include <stdint.h>

#define NTOK 4096
#define DMODEL 1024
#define DHID 4096
#define NEXP 8

// ================= scratch (device globals: allocation-free, keep SMALL) =================
__device__ int   g_expert[NTOK];
__device__ float g_gatew[NTOK];
__device__ int   g_counts[NEXP];
__device__ int   g_offsets[NEXP + 1];
__device__ int   g_cursor[NEXP];
__device__ int   g_perm[NTOK];
// grouped hidden, pre-split: [slot][0..DHID)=hi bf16, [DHID..2*DHID)=lo bf16 (64MB)
__device__ __align__(256) __nv_bfloat16 g_h[(size_t)NTOK * 2 * DHID];

__device__ __forceinline__ uint32_t smem_u32(const void* p) {
    uint32_t a;
    asm("{ .reg .u64 t; cvta.to.shared.u64 t, %1; cvt.u32.u64 %0, t; }" : "=r"(a) : "l"(p));
    return a;
}
__device__ __forceinline__ void mma16816(float* d, const uint32_t* a, uint32_t b0, uint32_t b1) {
    asm volatile("mma.sync.aligned.m16n8k16.row.col.f32.bf16.bf16.f32 "
        "{%0,%1,%2,%3}, {%4,%5,%6,%7}, {%8,%9}, {%0,%1,%2,%3};"
        : "+f"(d[0]), "+f"(d[1]), "+f"(d[2]), "+f"(d[3])
        : "r"(a[0]), "r"(a[1]), "r"(a[2]), "r"(a[3]), "r"(b0), "r"(b1));
}
__device__ __forceinline__ void ldsm_x4(uint32_t a, uint32_t& r0, uint32_t& r1,
                                        uint32_t& r2, uint32_t& r3) {
    asm volatile("ldmatrix.sync.aligned.m8n8.x4.shared.b16 {%0,%1,%2,%3}, [%4];"
        : "=r"(r0), "=r"(r1), "=r"(r2), "=r"(r3) : "r"(a));
}
// fast split: hi = truncate-to-bf16 (bit pack), lo = exact residual RN to bf16x2.
__device__ __forceinline__ void split2(float f0, float f1, uint32_t& hi, uint32_t& lo) {
    uint32_t u0 = __float_as_uint(f0), u1 = __float_as_uint(f1);
    hi = __byte_perm(u0, u1, 0x7632);
    float r0 = f0 - __uint_as_float(u0 & 0xFFFF0000u);
    float r1 = f1 - __uint_as_float(u1 & 0xFFFF0000u);
    __nv_bfloat162 p = __floats2bfloat162_rn(r0, r1);
    lo = *(uint32_t*)&p;
}

// ================= gating / routing (R1-proven) =================
__global__ void k_zero() {
    int t = threadIdx.x;
    if (t < NEXP) { g_counts[t] = 0; g_cursor[t] = 0; }
}
__global__ void k_gate(const float* __restrict__ x, const float* __restrict__ Wg,
                       const float* __restrict__ bg) {
    int tok = blockIdx.x * 8 + (threadIdx.x >> 5);
    int lane = threadIdx.x & 31;
    if (tok >= NTOK) return;
    float acc[NEXP];
#pragma unroll
    for (int e = 0; e < NEXP; e++) acc[e] = 0.f;
    const float* xr = x + (size_t)tok * DMODEL;
    for (int d = lane; d < DMODEL; d += 32) {
        float xv = xr[d];
        const float* wr = Wg + d * NEXP;
#pragma unroll
        for (int e = 0; e < NEXP; e++) acc[e] += xv * wr[e];
    }
#pragma unroll
    for (int e = 0; e < NEXP; e++)
#pragma unroll
        for (int o = 16; o > 0; o >>= 1) acc[e] += __shfl_xor_sync(0xffffffffu, acc[e], o);
    if (lane == 0) {
        float m = -1e30f; int arg = 0;
#pragma unroll
        for (int e = 0; e < NEXP; e++) {
            float l = acc[e] + bg[e]; acc[e] = l;
            if (l > m) { m = l; arg = e; }
        }
        float s = 0.f;
#pragma unroll
        for (int e = 0; e < NEXP; e++) s += expf(acc[e] - m);
        g_expert[tok] = arg;
        g_gatew[tok] = 1.0f / s;
        atomicAdd(&g_counts[arg], 1);
    }
}
__global__ void k_scan() {
    if (threadIdx.x == 0) {
        int acc = 0; g_offsets[0] = 0;
        for (int e = 0; e < NEXP; e++) {
            acc += g_counts[e];
            g_offsets[e + 1] = acc;
            g_cursor[e] = g_offsets[e];
        }
    }
}
__global__ void k_scatter() {
    int tok = blockIdx.x * blockDim.x + threadIdx.x;
    if (tok >= NTOK) return;
    int slot = atomicAdd(&g_cursor[g_expert[tok]], 1);
    g_perm[slot] = tok;
}

// ================= HMMA grouped GEMM, NS-stage pipeline =================
// BM=128, BN=128, BK=16 per stage. NS=2: 48KB static (fallback). NS=3: 72KB dynamic.
// Row stride 48B: ldmatrix conflict-free. Per stage: acc += Ahi*Bhi + Alo*Bhi + Ahi*Blo.
// 8 warps (4M x 2N), warp tile 32x64.
#define ROWB 48
#define STAGE 24576
#define AHI 0
#define ALO 6144
#define BHI 12288
#define BLO 18432

template <bool IS2, int NS>
__global__ __launch_bounds__(256, 2) void k_ffn_mma(const float* __restrict__ W,
                                                    const float* __restrict__ bias,
                                                    const float* __restrict__ x,
                                                    float* __restrict__ y) {
    constexpr int K  = IS2 ? DHID : DMODEL;
    constexpr int NN = IS2 ? DMODEL : DHID;
    constexpr int S  = K / 16;

    __shared__ __align__(16) char smem_s[NS == 2 ? 49152 : 16];
    extern __shared__ char smem_d[];
    char* smemc = (NS == 2) ? smem_s : smem_d;

    int e = blockIdx.z;
    int off = g_offsets[e];
    int cnt = g_offsets[e + 1] - off;
    int row0 = blockIdx.y * 128;
    if (row0 >= cnt) return;
    int col0 = blockIdx.x * 128;

    int tid = threadIdx.x, lane = tid & 31, wid = tid >> 5;
    int wm = wid & 3, wn = wid >> 2;
    int g = lane >> 2, q = lane & 3;
    uint32_t sb = smem_u32(smemc);

    // ---- staging assignments ----
    int arw = tid >> 1, kc = tid & 1;
    int aslot = off + row0 + arw; if (aslot > NTOK - 1) aslot = NTOK - 1;
    const float*         ax = nullptr;
    const __nv_bfloat16* ah = nullptr;
    if (IS2) ah = g_h + (size_t)aslot * (2 * DHID) + kc * 8;
    else     ax = x + (size_t)g_perm[aslot] * DMODEL + kc * 8;
    uint32_t asm_off = (uint32_t)(arw * ROWB + kc * 16);
    int bn = tid & 127, kg = tid >> 7;
    const float* bw = W + (size_t)e * K * NN + col0 + bn;
    uint32_t bsm_off = (uint32_t)(bn * ROWB + kg * 16);

    // ---- ldmatrix lane address offsets (within a stage buffer) ----
    uint32_t arel[2];
#pragma unroll
    for (int mt = 0; mt < 2; mt++) {
        int r = wm * 32 + mt * 16 + (lane & 7) + 8 * ((lane >> 3) & 1);
        arel[mt] = (uint32_t)(r * ROWB + (lane >> 4) * 16);
    }
    uint32_t brel[4];
#pragma unroll
    for (int p = 0; p < 4; p++) {
        int n = wn * 64 + p * 16 + (lane & 7) + 8 * (lane >> 4);
        brel[p] = (uint32_t)(n * ROWB + ((lane >> 3) & 1) * 16);
    }

    float acc[2][8][4];
#pragma unroll
    for (int i = 0; i < 2; i++)
#pragma unroll
        for (int j = 0; j < 8; j++)
#pragma unroll
            for (int p = 0; p < 4; p++) acc[i][j][p] = 0.f;

    float4 fa0, fa1;
    uint4  uahi, ualo;
    float  fb[8];

#define LDG_STAGE(GI) do {                                                     \
        int kk = (GI) * 16;                                                    \
        if (IS2) {                                                             \
            uahi = *(const uint4*)(ah + kk);                                   \
            ualo = *(const uint4*)(ah + DHID + kk);                            \
        } else {                                                               \
            fa0 = *(const float4*)(ax + kk);                                   \
            fa1 = *(const float4*)(ax + kk + 4);                               \
        }                                                                      \
        int kb = kk + kg * 8;                                                  \
        _Pragma("unroll")                                                      \
        for (int j = 0; j < 8; j++) fb[j] = bw[(size_t)(kb + j) * NN];         \
    } while (0)

#define STORE_STAGE(BUF) do {                                                  \
        char* s_ = smemc + (BUF) * STAGE;                                      \
        if (IS2) {                                                             \
            *(uint4*)(s_ + AHI + asm_off) = uahi;                              \
            *(uint4*)(s_ + ALO + asm_off) = ualo;                              \
        } else {                                                               \
            uint4 h_, l_;                                                      \
            split2(fa0.x, fa0.y, h_.x, l_.x);                                  \
            split2(fa0.z, fa0.w, h_.y, l_.y);                                  \
            split2(fa1.x, fa1.y, h_.z, l_.z);                                  \
            split2(fa1.z, fa1.w, h_.w, l_.w);                                  \
            *(uint4*)(s_ + AHI + asm_off) = h_;                                \
            *(uint4*)(s_ + ALO + asm_off) = l_;                                \
        }                                                                      \
        uint4 bh_, bl_;                                                        \
        split2(fb[0], fb[1], bh_.x, bl_.x);                                    \
        split2(fb[2], fb[3], bh_.y, bl_.y);                                    \
        split2(fb[4], fb[5], bh_.z, bl_.z);                                    \
        split2(fb[6], fb[7], bh_.w, bl_.w);                                    \
        *(uint4*)(s_ + BHI + bsm_off) = bh_;                                   \
        *(uint4*)(s_ + BLO + bsm_off) = bl_;                                   \
    } while (0)

    // prologue: fill NS-1 buffers, stage NS-1 in regs
#pragma unroll
    for (int p = 0; p < NS - 1; p++) { LDG_STAGE(p); STORE_STAGE(p); }
    LDG_STAGE(NS - 1);
    __syncthreads();

    for (int gi = 0; gi < S; gi++) {
        int bufc = gi; while (bufc >= NS) bufc -= NS;           // gi % NS (NS small)
        uint32_t sbuf = sb + (uint32_t)bufc * STAGE;
        // ---- compute stage gi ----
        uint32_t ahf[2][4], alf[2][4];
#pragma unroll
        for (int mt = 0; mt < 2; mt++) {
            ldsm_x4(sbuf + AHI + arel[mt], ahf[mt][0], ahf[mt][1], ahf[mt][2], ahf[mt][3]);
            ldsm_x4(sbuf + ALO + arel[mt], alf[mt][0], alf[mt][1], alf[mt][2], alf[mt][3]);
        }
#pragma unroll
        for (int p = 0; p < 4; p++) {
            uint32_t bh0, bh1, bh2, bh3, bl0, bl1, bl2, bl3;
            ldsm_x4(sbuf + BHI + brel[p], bh0, bh1, bh2, bh3);
            ldsm_x4(sbuf + BLO + brel[p], bl0, bl1, bl2, bl3);
            int n0 = p * 2, n1 = p * 2 + 1;
            mma16816(acc[0][n0], ahf[0], bh0, bh1);
            mma16816(acc[1][n0], ahf[1], bh0, bh1);
            mma16816(acc[0][n1], ahf[0], bh2, bh3);
            mma16816(acc[1][n1], ahf[1], bh2, bh3);
            mma16816(acc[0][n0], alf[0], bh0, bh1);
            mma16816(acc[1][n0], alf[1], bh0, bh1);
            mma16816(acc[0][n1], alf[0], bh2, bh3);
            mma16816(acc[1][n1], alf[1], bh2, bh3);
            mma16816(acc[0][n0], ahf[0], bl0, bl1);
            mma16816(acc[1][n0], ahf[1], bl0, bl1);
            mma16816(acc[0][n1], ahf[0], bl2, bl3);
            mma16816(acc[1][n1], ahf[1], bl2, bl3);
        }
        // ---- store stage gi+NS-1 (into buffer freed after stage gi-1) ----
        if (gi + NS - 1 < S) {
            int sbc = gi + NS - 1; while (sbc >= NS) sbc -= NS;
            STORE_STAGE(sbc);
        }
        // ---- prefetch stage gi+NS ----
        if (gi + NS < S) LDG_STAGE(gi + NS);
        __syncthreads();
    }
#undef LDG_STAGE
#undef STORE_STAGE

    // ================= epilogue =================
    const float* be_ = bias + (size_t)e * NN;
    int q2 = q * 2;
#pragma unroll
    for (int mt = 0; mt < 2; mt++) {
#pragma unroll
        for (int half = 0; half < 2; half++) {
            int ml = wm * 32 + mt * 16 + g + half * 8;
            if (row0 + ml >= cnt) continue;
            int slot = off + row0 + ml;
            if (!IS2) {
                __nv_bfloat16* hrow = g_h + (size_t)slot * (2 * DHID);
#pragma unroll
                for (int nt8 = 0; nt8 < 8; nt8++) {
                    int cg = col0 + wn * 64 + nt8 * 8 + q2;
                    float z0 = acc[mt][nt8][half * 2 + 0] + be_[cg];
                    float z1 = acc[mt][nt8][half * 2 + 1] + be_[cg + 1];
                    float s0 = z0 / (1.f + expf(-z0));
                    float s1 = z1 / (1.f + expf(-z1));
                    uint32_t hiw, low;
                    split2(s0, s1, hiw, low);
                    *(uint32_t*)(hrow + cg) = hiw;
                    *(uint32_t*)(hrow + DHID + cg) = low;
                }
            } else {
                int tok = g_perm[slot];
                float gw = g_gatew[tok];
                float* yrow = y + (size_t)tok * DMODEL;
#pragma unroll
                for (int nt8 = 0; nt8 < 8; nt8++) {
                    int cg = col0 + wn * 64 + nt8 * 8 + q2;
                    float2 o;
                    o.x = (acc[mt][nt8][half * 2 + 0] + be_[cg]) * gw;
                    o.y = (acc[mt][nt8][half * 2 + 1] + be_[cg + 1]) * gw;
                    *(float2*)(yrow + cg) = o;
                }
            }
        }
    }
}

// ================= launch =================
extern "C" void kernel_launch(void* const* d_in, const int* in_sizes, int n_in,
                              void* d_out, int out_size) {
    const float* x  = (const float*)d_in[0];
    const float* Wg = (const float*)d_in[1];
    const float* bg = (const float*)d_in[2];
    const float* W1 = (const float*)d_in[3];
    const float* b1 = (const float*)d_in[4];
    const float* W2 = (const float*)d_in[5];
    const float* b2 = (const float*)d_in[6];
    float* y = (float*)d_out;

    const int DSM = 3 * STAGE;   // 73728
    cudaError_t r1 = cudaFuncSetAttribute(k_ffn_mma<false, 3>,
                        cudaFuncAttributeMaxDynamicSharedMemorySize, DSM);
    cudaError_t r2 = cudaFuncSetAttribute(k_ffn_mma<true, 3>,
                        cudaFuncAttributeMaxDynamicSharedMemorySize, DSM);
    bool deep = (r1 == cudaSuccess) && (r2 == cudaSuccess);
    if (!deep) (void)cudaGetLastError();   // clear sticky error

    k_zero<<<1, 32>>>();
    k_gate<<<NTOK / 8, 256>>>(x, Wg, bg);
    k_scan<<<1, 1>>>();
    k_scatter<<<NTOK / 256, 256>>>();
    if (deep) {
        k_ffn_mma<false, 3><<<dim3(DHID / 128, NTOK / 128, NEXP), 256, DSM>>>(W1, b1, x, nullptr);
        k_ffn_mma<true, 3 ><<<dim3(DMODEL / 128, NTOK / 128, NEXP), 256, DSM>>>(W2, b2, x, y);
    } else {
        k_ffn_mma<false, 2><<<dim3(DHID / 128, NTOK / 128, NEXP), 256>>>(W1, b1, x, nullptr);
        k_ffn_mma<true, 2 ><<<dim3(DMODEL / 128, NTOK / 128, NEXP), 256>>>(W2, b2, x, y);
    }
}

// round 11
// speedup vs baseline: 1.0364x; 1.0364x over previous
#include <cuda_runtime.h>
#include <cuda_bf16.h>
#include <math.h>
#include <stdint.h>

#define NTOK 4096
#define DMODEL 1024
#define DHID 4096
#define NEXP 8

// ================= scratch (device globals: allocation-free, keep SMALL) =================
__device__ int   g_expert[NTOK];
__device__ float g_gatew[NTOK];
__device__ int   g_counts[NEXP];
__device__ int   g_offsets[NEXP + 1];
__device__ int   g_cursor[NEXP];
__device__ int   g_perm[NTOK];
// grouped hidden, pre-split: [slot][0..DHID)=hi bf16, [DHID..2*DHID)=lo bf16 (64MB)
__device__ __align__(256) __nv_bfloat16 g_h[(size_t)NTOK * 2 * DHID];

__device__ __forceinline__ uint32_t smem_u32(const void* p) {
    uint32_t a;
    asm("{ .reg .u64 t; cvta.to.shared.u64 t, %1; cvt.u32.u64 %0, t; }" : "=r"(a) : "l"(p));
    return a;
}
__device__ __forceinline__ void mma16816(float* d, const uint32_t* a, uint32_t b0, uint32_t b1) {
    asm volatile("mma.sync.aligned.m16n8k16.row.col.f32.bf16.bf16.f32 "
        "{%0,%1,%2,%3}, {%4,%5,%6,%7}, {%8,%9}, {%0,%1,%2,%3};"
        : "+f"(d[0]), "+f"(d[1]), "+f"(d[2]), "+f"(d[3])
        : "r"(a[0]), "r"(a[1]), "r"(a[2]), "r"(a[3]), "r"(b0), "r"(b1));
}
__device__ __forceinline__ void ldsm_x4(uint32_t a, uint32_t& r0, uint32_t& r1,
                                        uint32_t& r2, uint32_t& r3) {
    asm volatile("ldmatrix.sync.aligned.m8n8.x4.shared.b16 {%0,%1,%2,%3}, [%4];"
        : "=r"(r0), "=r"(r1), "=r"(r2), "=r"(r3) : "r"(a));
}
#define CPA16(dst, src) \
    asm volatile("cp.async.cg.shared.global [%0], [%1], 16;" :: "r"(dst), "l"(src))
#define CP_COMMIT() asm volatile("cp.async.commit_group;" ::: "memory")
#define CP_WAIT1()  asm volatile("cp.async.wait_group 1;" ::: "memory")

// fast split: hi = truncate-to-bf16 (bit pack), lo = exact residual RN to bf16x2.
__device__ __forceinline__ void split2(float f0, float f1, uint32_t& hi, uint32_t& lo) {
    uint32_t u0 = __float_as_uint(f0), u1 = __float_as_uint(f1);
    hi = __byte_perm(u0, u1, 0x7632);
    float r0 = f0 - __uint_as_float(u0 & 0xFFFF0000u);
    float r1 = f1 - __uint_as_float(u1 & 0xFFFF0000u);
    __nv_bfloat162 p = __floats2bfloat162_rn(r0, r1);
    lo = *(uint32_t*)&p;
}

// ================= gating / routing (R1-proven) =================
__global__ void k_zero() {
    int t = threadIdx.x;
    if (t < NEXP) { g_counts[t] = 0; g_cursor[t] = 0; }
}
__global__ void k_gate(const float* __restrict__ x, const float* __restrict__ Wg,
                       const float* __restrict__ bg) {
    int tok = blockIdx.x * 8 + (threadIdx.x >> 5);
    int lane = threadIdx.x & 31;
    if (tok >= NTOK) return;
    float acc[NEXP];
#pragma unroll
    for (int e = 0; e < NEXP; e++) acc[e] = 0.f;
    const float* xr = x + (size_t)tok * DMODEL;
    for (int d = lane; d < DMODEL; d += 32) {
        float xv = xr[d];
        const float* wr = Wg + d * NEXP;
#pragma unroll
        for (int e = 0; e < NEXP; e++) acc[e] += xv * wr[e];
    }
#pragma unroll
    for (int e = 0; e < NEXP; e++)
#pragma unroll
        for (int o = 16; o > 0; o >>= 1) acc[e] += __shfl_xor_sync(0xffffffffu, acc[e], o);
    if (lane == 0) {
        float m = -1e30f; int arg = 0;
#pragma unroll
        for (int e = 0; e < NEXP; e++) {
            float l = acc[e] + bg[e]; acc[e] = l;
            if (l > m) { m = l; arg = e; }
        }
        float s = 0.f;
#pragma unroll
        for (int e = 0; e < NEXP; e++) s += expf(acc[e] - m);
        g_expert[tok] = arg;
        g_gatew[tok] = 1.0f / s;
        atomicAdd(&g_counts[arg], 1);
    }
}
__global__ void k_scan() {
    if (threadIdx.x == 0) {
        int acc = 0; g_offsets[0] = 0;
        for (int e = 0; e < NEXP; e++) {
            acc += g_counts[e];
            g_offsets[e + 1] = acc;
            g_cursor[e] = g_offsets[e];
        }
    }
}
__global__ void k_scatter() {
    int tok = blockIdx.x * blockDim.x + threadIdx.x;
    if (tok >= NTOK) return;
    int slot = atomicAdd(&g_cursor[g_expert[tok]], 1);
    g_perm[slot] = tok;
}

// ================= HMMA grouped GEMM: cp.async ring + split-from-smem =================
// bf16 compute tiles: 2 stages x 24576B (R8 layout). Staging ring: 3 stages x 16384B.
// Schedule per iter gi: ISSUE(gi+3) | compute(gi) | SPLIT(gi+1) | CP_WAIT1 | sync.
// The wait+sync at end of iter gi-1 makes ALL threads' stage-(gi+1) copies visible
// before SPLIT(gi+1) reads them cross-thread (the R10 race, fixed).
#define ROWB 48
#define TSTAGE 24576
#define AHI 0
#define ALO 6144
#define BHI 12288
#define BLO 18432
#define RINGOFF 49152
#define RSTAGE 16384
#define DSMEM 98304

template <bool IS2>
__global__ __launch_bounds__(256, 2) void k_ffn_mma(const float* __restrict__ W,
                                                    const float* __restrict__ bias,
                                                    const float* __restrict__ x,
                                                    float* __restrict__ y) {
    constexpr int K  = IS2 ? DHID : DMODEL;
    constexpr int NN = IS2 ? DMODEL : DHID;
    constexpr int S  = K / 16;

    extern __shared__ __align__(16) char smemc[];

    int e = blockIdx.z;
    int off = g_offsets[e];
    int cnt = g_offsets[e + 1] - off;
    int row0 = blockIdx.y * 128;
    if (row0 >= cnt) return;
    int col0 = blockIdx.x * 128;

    int tid = threadIdx.x, lane = tid & 31, wid = tid >> 5;
    int wm = wid & 3, wn = wid >> 2;
    int g = lane >> 2, q = lane & 3;
    uint32_t sb = smem_u32(smemc);

    // ---- cp.async source/dest assignments ----
    const float*         a1src[2];  uint32_t a1dst[2];   // FFN1 A fp32
    const __nv_bfloat16* a2src[2];  uint32_t a2dst[2];   // FFN2 A bf16 (hi,lo)
    const float*         bsrc[2];   uint32_t bdst[2];    // B fp32
#pragma unroll
    for (int t = 0; t < 2; t++) {
        int c = tid + t * 256;
        if (!IS2) {
            int row = c >> 2, q4 = c & 3;
            int slot = off + row0 + row; if (slot > NTOK - 1) slot = NTOK - 1;
            a1src[t] = x + (size_t)g_perm[slot] * DMODEL + q4 * 4;
            a1dst[t] = (uint32_t)(row * 64 + q4 * 16);
        }
        int krow = c >> 5, n4 = c & 31;
        bsrc[t] = W + (size_t)e * K * NN + (size_t)krow * NN + col0 + n4 * 4;
        bdst[t] = (uint32_t)(8192 + krow * 512 + n4 * 16);
    }
    if (IS2) {
        int row = tid >> 1, half = tid & 1;
        int slot = off + row0 + row; if (slot > NTOK - 1) slot = NTOK - 1;
        const __nv_bfloat16* hb = g_h + (size_t)slot * (2 * DHID);
        a2src[0] = hb + half * 8;        a2dst[0] = (uint32_t)(row * 32 + half * 16);
        a2src[1] = hb + DHID + half * 8; a2dst[1] = (uint32_t)(4096 + row * 32 + half * 16);
    }
    // split-phase offsets
    uint32_t asm_off = (uint32_t)((tid >> 1) * ROWB + (tid & 1) * 16);
    int bn = tid & 127, kg = tid >> 7;
    uint32_t bsm_off = (uint32_t)(bn * ROWB + kg * 16);

    // ---- ldmatrix lane address offsets (within a bf16 tile buffer) ----
    uint32_t arel[2];
#pragma unroll
    for (int mt = 0; mt < 2; mt++) {
        int r = wm * 32 + mt * 16 + (lane & 7) + 8 * ((lane >> 3) & 1);
        arel[mt] = (uint32_t)(r * ROWB + (lane >> 4) * 16);
    }
    uint32_t brel[4];
#pragma unroll
    for (int p = 0; p < 4; p++) {
        int n = wn * 64 + p * 16 + (lane & 7) + 8 * (lane >> 4);
        brel[p] = (uint32_t)(n * ROWB + ((lane >> 3) & 1) * 16);
    }

    float acc[2][8][4];
#pragma unroll
    for (int i = 0; i < 2; i++)
#pragma unroll
        for (int j = 0; j < 8; j++)
#pragma unroll
            for (int p = 0; p < 4; p++) acc[i][j][p] = 0.f;

#define ISSUE_RING(GI, RB) do {                                                \
        uint32_t rb_ = sb + RINGOFF + (uint32_t)(RB) * RSTAGE;                 \
        int kk_ = (GI) * 16;                                                   \
        if (IS2) {                                                             \
            CPA16(rb_ + a2dst[0], a2src[0] + kk_);                             \
            CPA16(rb_ + a2dst[1], a2src[1] + kk_);                             \
        } else {                                                               \
            CPA16(rb_ + a1dst[0], a1src[0] + kk_);                             \
            CPA16(rb_ + a1dst[1], a1src[1] + kk_);                             \
        }                                                                      \
        CPA16(rb_ + bdst[0], bsrc[0] + (size_t)kk_ * NN);                      \
        CPA16(rb_ + bdst[1], bsrc[1] + (size_t)kk_ * NN);                      \
        CP_COMMIT();                                                           \
    } while (0)

#define SPLIT_STAGE(RB, TB) do {                                               \
        char* rbp = smemc + RINGOFF + (RB) * RSTAGE;                           \
        char* tbp = smemc + (TB) * TSTAGE;                                     \
        if (IS2) {                                                             \
            *(uint4*)(tbp + AHI + asm_off) = *(const uint4*)(rbp + a2dst[0]);  \
            *(uint4*)(tbp + ALO + asm_off) = *(const uint4*)(rbp + a2dst[1]);  \
        } else {                                                               \
            float4 fa0 = *(const float4*)(rbp + (tid >> 1) * 64 + (tid & 1) * 32);      \
            float4 fa1 = *(const float4*)(rbp + (tid >> 1) * 64 + (tid & 1) * 32 + 16); \
            uint4 h_, l_;                                                      \
            split2(fa0.x, fa0.y, h_.x, l_.x);                                  \
            split2(fa0.z, fa0.w, h_.y, l_.y);                                  \
            split2(fa1.x, fa1.y, h_.z, l_.z);                                  \
            split2(fa1.z, fa1.w, h_.w, l_.w);                                  \
            *(uint4*)(tbp + AHI + asm_off) = h_;                               \
            *(uint4*)(tbp + ALO + asm_off) = l_;                               \
        }                                                                      \
        float fb0 = *(const float*)(rbp + 8192 + (kg * 8 + 0) * 512 + bn * 4); \
        float fb1 = *(const float*)(rbp + 8192 + (kg * 8 + 1) * 512 + bn * 4); \
        float fb2 = *(const float*)(rbp + 8192 + (kg * 8 + 2) * 512 + bn * 4); \
        float fb3 = *(const float*)(rbp + 8192 + (kg * 8 + 3) * 512 + bn * 4); \
        float fb4 = *(const float*)(rbp + 8192 + (kg * 8 + 4) * 512 + bn * 4); \
        float fb5 = *(const float*)(rbp + 8192 + (kg * 8 + 5) * 512 + bn * 4); \
        float fb6 = *(const float*)(rbp + 8192 + (kg * 8 + 6) * 512 + bn * 4); \
        float fb7 = *(const float*)(rbp + 8192 + (kg * 8 + 7) * 512 + bn * 4); \
        uint4 bh_, bl_;                                                        \
        split2(fb0, fb1, bh_.x, bl_.x);                                        \
        split2(fb2, fb3, bh_.y, bl_.y);                                        \
        split2(fb4, fb5, bh_.z, bl_.z);                                        \
        split2(fb6, fb7, bh_.w, bl_.w);                                        \
        *(uint4*)(tbp + BHI + bsm_off) = bh_;                                  \
        *(uint4*)(tbp + BLO + bsm_off) = bl_;                                  \
    } while (0)

    // prologue: fill ring stages 0,1,2; make stage 0 tiles; publish to all threads
    ISSUE_RING(0, 0);
    ISSUE_RING(1, 1);
    ISSUE_RING(2, 2);
    CP_WAIT1();          // own copies of stages 0,1 complete
    __syncthreads();     // ALL threads' stages 0,1 visible
    SPLIT_STAGE(0, 0);
    __syncthreads();     // tile 0 visible

    int rb_issue = 0;    // ring buf of stage gi+3 ((gi+3)%3 == gi%3)
    int rb_split = 1;    // ring buf of stage gi+1
    for (int gi = 0; gi < S; gi++) {
        if (gi + 3 < S) ISSUE_RING(gi + 3, rb_issue); else CP_COMMIT();
        // ---- compute stage gi ----
        uint32_t sbuf = sb + (uint32_t)(gi & 1) * TSTAGE;
        uint32_t ahf[2][4], alf[2][4];
#pragma unroll
        for (int mt = 0; mt < 2; mt++) {
            ldsm_x4(sbuf + AHI + arel[mt], ahf[mt][0], ahf[mt][1], ahf[mt][2], ahf[mt][3]);
            ldsm_x4(sbuf + ALO + arel[mt], alf[mt][0], alf[mt][1], alf[mt][2], alf[mt][3]);
        }
#pragma unroll
        for (int p = 0; p < 4; p++) {
            uint32_t bh0, bh1, bh2, bh3, bl0, bl1, bl2, bl3;
            ldsm_x4(sbuf + BHI + brel[p], bh0, bh1, bh2, bh3);
            ldsm_x4(sbuf + BLO + brel[p], bl0, bl1, bl2, bl3);
            int n0 = p * 2, n1 = p * 2 + 1;
            mma16816(acc[0][n0], ahf[0], bh0, bh1);
            mma16816(acc[1][n0], ahf[1], bh0, bh1);
            mma16816(acc[0][n1], ahf[0], bh2, bh3);
            mma16816(acc[1][n1], ahf[1], bh2, bh3);
            mma16816(acc[0][n0], alf[0], bh0, bh1);
            mma16816(acc[1][n0], alf[1], bh0, bh1);
            mma16816(acc[0][n1], alf[0], bh2, bh3);
            mma16816(acc[1][n1], alf[1], bh2, bh3);
            mma16816(acc[0][n0], ahf[0], bl0, bl1);
            mma16816(acc[1][n0], ahf[1], bl0, bl1);
            mma16816(acc[0][n1], ahf[0], bl2, bl3);
            mma16816(acc[1][n1], ahf[1], bl2, bl3);
        }
        // ---- split stage gi+1 (ring data published by wait+sync of iter gi-1) ----
        if (gi + 1 < S) SPLIT_STAGE(rb_split, (gi + 1) & 1);
        CP_WAIT1();        // own copies through stage gi+2 complete
        __syncthreads();   // publish stage gi+2 ring data + tile (gi+1)&1
        if (++rb_issue == 3) rb_issue = 0;
        if (++rb_split == 3) rb_split = 0;
    }
#undef ISSUE_RING
#undef SPLIT_STAGE

    // ================= epilogue =================
    const float* be_ = bias + (size_t)e * NN;
    int q2 = q * 2;
#pragma unroll
    for (int mt = 0; mt < 2; mt++) {
#pragma unroll
        for (int half = 0; half < 2; half++) {
            int ml = wm * 32 + mt * 16 + g + half * 8;
            if (row0 + ml >= cnt) continue;
            int slot = off + row0 + ml;
            if (!IS2) {
                __nv_bfloat16* hrow = g_h + (size_t)slot * (2 * DHID);
#pragma unroll
                for (int nt8 = 0; nt8 < 8; nt8++) {
                    int cg = col0 + wn * 64 + nt8 * 8 + q2;
                    float z0 = acc[mt][nt8][half * 2 + 0] + be_[cg];
                    float z1 = acc[mt][nt8][half * 2 + 1] + be_[cg + 1];
                    float s0 = z0 / (1.f + expf(-z0));
                    float s1 = z1 / (1.f + expf(-z1));
                    uint32_t hiw, low;
                    split2(s0, s1, hiw, low);
                    *(uint32_t*)(hrow + cg) = hiw;
                    *(uint32_t*)(hrow + DHID + cg) = low;
                }
            } else {
                int tok = g_perm[slot];
                float gw = g_gatew[tok];
                float* yrow = y + (size_t)tok * DMODEL;
#pragma unroll
                for (int nt8 = 0; nt8 < 8; nt8++) {
                    int cg = col0 + wn * 64 + nt8 * 8 + q2;
                    float2 o;
                    o.x = (acc[mt][nt8][half * 2 + 0] + be_[cg]) * gw;
                    o.y = (acc[mt][nt8][half * 2 + 1] + be_[cg + 1]) * gw;
                    *(float2*)(yrow + cg) = o;
                }
            }
        }
    }
}

// ================= launch =================
extern "C" void kernel_launch(void* const* d_in, const int* in_sizes, int n_in,
                              void* d_out, int out_size) {
    const float* x  = (const float*)d_in[0];
    const float* Wg = (const float*)d_in[1];
    const float* bg = (const float*)d_in[2];
    const float* W1 = (const float*)d_in[3];
    const float* b1 = (const float*)d_in[4];
    const float* W2 = (const float*)d_in[5];
    const float* b2 = (const float*)d_in[6];
    float* y = (float*)d_out;

    cudaFuncSetAttribute(k_ffn_mma<false>, cudaFuncAttributeMaxDynamicSharedMemorySize, DSMEM);
    cudaFuncSetAttribute(k_ffn_mma<true>,  cudaFuncAttributeMaxDynamicSharedMemorySize, DSMEM);

    k_zero<<<1, 32>>>();
    k_gate<<<NTOK / 8, 256>>>(x, Wg, bg);
    k_scan<<<1, 1>>>();
    k_scatter<<<NTOK / 256, 256>>>();
    k_ffn_mma<false><<<dim3(DHID / 128, NTOK / 128, NEXP), 256, DSMEM>>>(W1, b1, x, nullptr);
    k_ffn_mma<true ><<<dim3(DMODEL / 128, NTOK / 128, NEXP), 256, DSMEM>>>(W2, b2, x, y);
}